// round 4
// baseline (speedup 1.0000x reference)
#include <cuda_runtime.h>
#include <cuda_fp16.h>

#define NN   110
#define BB   2048
#define NH1  5
#define F1   24
#define HF1  120   // NH1*F1
#define NH2  3
#define F2   3
#define ALPHA 0.2f
#define NT   512

#define XS_STRIDE 113
#define XS_ROWS   112

// ---- shared memory layout (float offsets) ----
#define OFF_XS   0
#define SZ_XS    (XS_ROWS*XS_STRIDE)          // 12656 : Xm, then P, then layer-2 scratch
#define OFF_FEH  (OFF_XS + SZ_XS)             // feats fp16
#define SZ_FEH   (NN*HF1/2)
#define OFF_H1H  (OFF_FEH + SZ_FEH)           // h1 fp16
#define SZ_H1H   (NN*HF1/2)
#define OFF_ES1  (OFF_H1H + SZ_H1H)           // 550
#define OFF_EN1  (OFF_ES1 + NH1*NN)           // 550
#define OFF_ZS   (OFF_EN1 + NH1*NN)           // 110
#define OFF_MXE  (OFF_ZS + NN)                // 8 (maxEn for both layers)
#define OFF_AM   (OFF_MXE + 8)                // 440 uint32 words
#define SMEM_FLOATS (OFF_AM + NN*4)
#define SMEM_BYTES  (SMEM_FLOATS*4)           // ~110KB -> 2 CTAs/SM

// layer-2 scratch aliased into the (dead) Xs/P region:
#define L2_F2S  0        // 990
#define L2_HO2  990      // 990
#define L2_ES2  1980     // 330
#define L2_EN2  2310     // 330
#define L2_TS   2640     // 110
#define L2_YS   2752     // 112

__device__ float g_sigM[NN*NN];
__device__ float g_W1t[NN*HF1];   // [k][h*F1+f]
__device__ float g_W2t[9*HF1];    // [h*3+f][k2]

__global__ void prep_kernel(const float* __restrict__ M, const float* __restrict__ W1,
                            const float* __restrict__ W2) {
    int i = blockIdx.x*blockDim.x + threadIdx.x;
    if (i < NN*NN) g_sigM[i] = 1.f/(1.f + expf(-M[i]));
    if (i < NN*HF1) {
        int k = i / HF1, hf = i - k*HF1;
        int h = hf / F1, f = hf - h*F1;
        g_W1t[i] = W1[(h*NN + k)*F1 + f];
    }
    if (i < 9*HF1) {
        int c = i / HF1, k2 = i - c*HF1;
        int h = c / 3, f = c - h*3;
        g_W2t[i] = W2[(h*HF1 + k2)*F2 + f];
    }
}

__device__ __forceinline__ float wred_max(float v) {
    #pragma unroll
    for (int o = 16; o > 0; o >>= 1) v = fmaxf(v, __shfl_xor_sync(0xffffffffu, v, o));
    return v;
}
__device__ __forceinline__ float wred_sum(float v) {
    #pragma unroll
    for (int o = 16; o > 0; o >>= 1) v += __shfl_xor_sync(0xffffffffu, v, o);
    return v;
}

// ---- packed f32x2 helpers (Blackwell) ----
__device__ __forceinline__ unsigned long long pack2(float a, float b) {
    unsigned long long r;
    asm("mov.b64 %0, {%1, %2};" : "=l"(r) : "f"(a), "f"(b));
    return r;
}
__device__ __forceinline__ float2 unpack2(unsigned long long v) {
    float2 r;
    asm("mov.b64 {%0, %1}, %2;" : "=f"(r.x), "=f"(r.y) : "l"(v));
    return r;
}
__device__ __forceinline__ void ffma2(unsigned long long& d, unsigned long long a,
                                      unsigned long long b) {
    asm("fma.rn.f32x2 %0, %1, %2, %0;" : "+l"(d) : "l"(a), "l"(b));
}

__global__ __launch_bounds__(NT, 2)
void gat_kernel(const float* __restrict__ X, const float* __restrict__ A,
                const float* __restrict__ as1, const float* __restrict__ an1,
                const float* __restrict__ b1,
                const float* __restrict__ as2,
                const float* __restrict__ an2, const float* __restrict__ b2,
                const float* __restrict__ fc1, const float* __restrict__ fc2,
                float* __restrict__ out)
{
    extern __shared__ float sm[];
    float*    Xs     = sm + OFF_XS;            // Xm -> P -> layer2 scratch
    __half*   featsH = (__half*)(sm + OFF_FEH);
    __half*   h1H    = (__half*)(sm + OFF_H1H);
    float*    es1    = sm + OFF_ES1;
    float*    en1    = sm + OFF_EN1;
    float*    Zs     = sm + OFF_ZS;
    float*    maxEnS = sm + OFF_MXE;
    unsigned* Amask  = (unsigned*)(sm + OFF_AM);

    const int b = blockIdx.x;
    const int t = threadIdx.x;
    const int w = t >> 5, lane = t & 31;
    const float* Xb = X + (size_t)b*NN*NN;
    const float* Ab = A + (size_t)b*NN*NN;

    // ---- stage 1: Xm into smem, adjacency bitmask --------------------------
    for (int i = t; i < NN*NN; i += NT) {
        int n = i / NN, k = i - n*NN;
        Xs[n*XS_STRIDE + k] = Xb[i] * g_sigM[i];
    }
    for (int i = t; i < 2*XS_STRIDE; i += NT) Xs[NN*XS_STRIDE + i] = 0.f;  // pad rows 110,111
    for (int task = w; task < NN*4; task += 16) {
        int n = task >> 2, q = task & 3;
        int j = q*32 + lane;
        bool pred = (j < NN) && (Ab[n*NN + j] > 0.f);
        unsigned word = __ballot_sync(0xffffffffu, pred);
        if (lane == 0) Amask[task] = word;
    }
    __syncthreads();

    // ---- GEMM1: feats = Xm @ W1t (FFMA2), fused exact-fp32 es/en epilogue --
    {
        const unsigned GM = 0x3fffffffu;
        if (lane < 30) {
            const int ct = lane;
            const int n0 = w * 7;
            unsigned long long acc2[7][2];
            #pragma unroll
            for (int r = 0; r < 7; r++) { acc2[r][0] = 0ull; acc2[r][1] = 0ull; }
            const ulonglong2* Wg = (const ulonglong2*)g_W1t;   // (w0,w1),(w2,w3) packed
            #pragma unroll 2
            for (int k = 0; k < NN; k++) {
                ulonglong2 wv = __ldg(Wg + k*30 + ct);
                #pragma unroll
                for (int r = 0; r < 7; r++) {
                    float xv = Xs[(n0+r)*XS_STRIDE + k];    // broadcast within warp
                    unsigned long long xx = pack2(xv, xv);
                    ffma2(acc2[r][0], xx, wv.x);
                    ffma2(acc2[r][1], xx, wv.y);
                }
            }
            const int h  = ct / 6;
            const int f0 = (ct - h*6) * 4;
            float a0 = __ldg(as1 + h*F1 + f0),     a1 = __ldg(as1 + h*F1 + f0 + 1);
            float a2 = __ldg(as1 + h*F1 + f0 + 2), a3 = __ldg(as1 + h*F1 + f0 + 3);
            float c0 = __ldg(an1 + h*F1 + f0),     c1 = __ldg(an1 + h*F1 + f0 + 1);
            float c2 = __ldg(an1 + h*F1 + f0 + 2), c3 = __ldg(an1 + h*F1 + f0 + 3);
            const int base = h*6;
            #pragma unroll
            for (int r = 0; r < 7; r++) {
                int n = n0 + r;
                float pes = 0.f, pen = 0.f;
                if (n < NN) {
                    float2 v01 = unpack2(acc2[r][0]);
                    float2 v23 = unpack2(acc2[r][1]);
                    __half2* fp = (__half2*)(featsH + n*HF1 + ct*4);
                    fp[0] = __floats2half2_rn(v01.x, v01.y);
                    fp[1] = __floats2half2_rn(v23.x, v23.y);
                    pes = v01.x*a0 + v01.y*a1 + v23.x*a2 + v23.y*a3;
                    pen = v01.x*c0 + v01.y*c1 + v23.x*c2 + v23.y*c3;
                }
                float te = 0.f, tn = 0.f;
                #pragma unroll
                for (int i = 0; i < 6; i++) {
                    te += __shfl_sync(GM, pes, base + i);
                    tn += __shfl_sync(GM, pen, base + i);
                }
                if (ct == base && n < NN) { es1[h*NN + n] = te; en1[h*NN + n] = tn; }
            }
        }
    }
    __syncthreads();

    // ---- per-head global max of en (for overflow-safe softmax shift) -------
    if (w < NH1) {
        float mv = -1e30f;
        #pragma unroll
        for (int q = 0; q < 4; q++) {
            int j = q*32 + lane;
            if (j < NN) mv = fmaxf(mv, en1[w*NN + j]);
        }
        mv = wred_max(mv);
        if (lane == 0) maxEnS[w] = mv;
    }
    __syncthreads();

    float* Ps = Xs;    // Xm no longer needed

    // ---- per-head masked softmax + aggregate ------------------------------
    for (int h = 0; h < NH1; h++) {
        // softmax rows: shift by m = lrelu(es_r + maxEn_h) >= true masked max
        for (int row = w; row < NN; row += 16) {
            float esr = es1[h*NN + row];
            float m = esr + maxEnS[h];
            m = fmaxf(m, ALPHA*m);
            float s = 0.f;
            #pragma unroll
            for (int q = 0; q < 4; q++) {
                int j = q*32 + lane;
                if (j < NN) {
                    unsigned bit = (Amask[row*4 + q] >> lane) & 1u;
                    float e = esr + en1[h*NN + j];
                    e = fmaxf(e, ALPHA*e);
                    float p = bit ? __expf(e - m) : 0.f;
                    Ps[row*XS_STRIDE + j] = p;
                    s += p;
                }
            }
            s = wred_sum(s);
            if (lane == 0) Zs[row] = s;
        }
        __syncthreads();

        // aggregate: h1[n][h*24+f] = lrelu( (P[n]·feats[:, h*24+f]) / Z[n] + b1[f] )
        if (t < 330) {
            int rt = t / 6, ct = t - (t/6)*6;   // 55 row tiles of 2, 6 f-tiles of 4
            int n0 = rt * 2;
            unsigned long long a00 = 0ull, a01 = 0ull, a10 = 0ull, a11 = 0ull;
            const uint2* Fv = (const uint2*)featsH;   // 4 halves per load
            #pragma unroll 2
            for (int k = 0; k < NN; k++) {
                uint2 fv = Fv[k*30 + h*6 + ct];
                float2 f01 = __half22float2(*reinterpret_cast<__half2*>(&fv.x));
                float2 f23 = __half22float2(*reinterpret_cast<__half2*>(&fv.y));
                unsigned long long F01 = pack2(f01.x, f01.y);
                unsigned long long F23 = pack2(f23.x, f23.y);
                float p0 = Ps[n0*XS_STRIDE + k];
                float p1 = Ps[(n0+1)*XS_STRIDE + k];
                unsigned long long P0 = pack2(p0, p0);
                unsigned long long P1 = pack2(p1, p1);
                ffma2(a00, P0, F01); ffma2(a01, P0, F23);
                ffma2(a10, P1, F01); ffma2(a11, P1, F23);
            }
            float bb0 = __ldg(b1 + ct*4 + 0), bb1 = __ldg(b1 + ct*4 + 1);
            float bb2 = __ldg(b1 + ct*4 + 2), bb3 = __ldg(b1 + ct*4 + 3);
            #pragma unroll
            for (int r = 0; r < 2; r++) {
                int n = n0 + r;
                float invZ = 1.f / Zs[n];
                float2 v01 = unpack2(r == 0 ? a00 : a10);
                float2 v23 = unpack2(r == 0 ? a01 : a11);
                float v0 = fmaf(v01.x, invZ, bb0);
                float v1 = fmaf(v01.y, invZ, bb1);
                float v2 = fmaf(v23.x, invZ, bb2);
                float v3 = fmaf(v23.y, invZ, bb3);
                v0 = fmaxf(v0, ALPHA*v0); v1 = fmaxf(v1, ALPHA*v1);
                v2 = fmaxf(v2, ALPHA*v2); v3 = fmaxf(v3, ALPHA*v3);
                __half2* hp = (__half2*)(h1H + n*HF1 + h*F1 + ct*4);
                hp[0] = __floats2half2_rn(v0, v1);
                hp[1] = __floats2half2_rn(v2, v3);
            }
        }
        __syncthreads();
    }

    // layer-2 scratch aliases the P region (dead now)
    float* f2s = Xs + L2_F2S;
    float* ho2 = Xs + L2_HO2;
    float* es2 = Xs + L2_ES2;
    float* en2 = Xs + L2_EN2;
    float* ts  = Xs + L2_TS;
    float* ys  = Xs + L2_YS;

    // ---- layer 2: projections f2s[n][c] = h1[n]·W2t[c] (FFMA2) ------------
    for (int i = t; i < NN*9; i += NT) {
        int n = i / 9, c = i - n*9;
        const __half* hr = h1H + n*HF1;
        const unsigned long long* wp = (const unsigned long long*)(g_W2t + c*HF1);
        unsigned long long acc = 0ull;
        #pragma unroll 4
        for (int k2 = 0; k2 < HF1/2; k2++) {
            float2 fv = __half22float2(*(const __half2*)(hr + 2*k2));
            unsigned long long hv = pack2(fv.x, fv.y);
            ffma2(acc, hv, __ldg(wp + k2));
        }
        float2 r = unpack2(acc);
        f2s[i] = r.x + r.y;
    }
    __syncthreads();
    for (int i = t; i < NH2*NN; i += NT) {
        int h = i / NN, n = i - h*NN;
        const float* fr = f2s + n*9 + h*3;
        float a = fr[0]*__ldg(as2+h*3) + fr[1]*__ldg(as2+h*3+1) + fr[2]*__ldg(as2+h*3+2);
        float c = fr[0]*__ldg(an2+h*3) + fr[1]*__ldg(an2+h*3+1) + fr[2]*__ldg(an2+h*3+2);
        es2[i] = a; en2[i] = c;
    }
    __syncthreads();
    if (w < NH2) {
        float mv = -1e30f;
        #pragma unroll
        for (int q = 0; q < 4; q++) {
            int j = q*32 + lane;
            if (j < NN) mv = fmaxf(mv, en2[w*NN + j]);
        }
        mv = wred_max(mv);
        if (lane == 0) maxEnS[NH1 + w] = mv;
    }
    __syncthreads();

    // ---- layer-2 softmax + aggregate (warp per (h,row)) -------------------
    for (int task = w; task < NH2*NN; task += 16) {
        int h = task / NN, n = task - h*NN;
        float esr = es2[task];
        float m = esr + maxEnS[NH1 + h];
        m = fmaxf(m, ALPHA*m);
        float s0 = 0.f, s1 = 0.f, s2 = 0.f, s3 = 0.f;
        #pragma unroll
        for (int q = 0; q < 4; q++) {
            int j = q*32 + lane;
            if (j < NN) {
                unsigned bit = (Amask[n*4 + q] >> lane) & 1u;
                if (bit) {
                    float e = esr + en2[h*NN + j];
                    e = fmaxf(e, ALPHA*e);
                    float p = __expf(e - m);
                    const float* fj = f2s + j*9 + h*3;
                    s0 += p;
                    s1 = fmaf(p, fj[0], s1);
                    s2 = fmaf(p, fj[1], s2);
                    s3 = fmaf(p, fj[2], s3);
                }
            }
        }
        s0 = wred_sum(s0); s1 = wred_sum(s1); s2 = wred_sum(s2); s3 = wred_sum(s3);
        if (lane == 0) {
            float inv = 1.f / s0;
            ho2[n*9 + h*3 + 0] = s1*inv;
            ho2[n*9 + h*3 + 1] = s2*inv;
            ho2[n*9 + h*3 + 2] = s3*inv;
        }
    }
    __syncthreads();

    // ---- head mean + lrelu + fc1 + sigmoid --------------------------------
    if (t < NN) {
        int n = t;
        float s = 0.f;
        #pragma unroll
        for (int f = 0; f < 3; f++) {
            float v = (ho2[n*9 + f] + ho2[n*9 + 3 + f] + ho2[n*9 + 6 + f]) * (1.f/3.f)
                      + __ldg(b2 + f);
            v = fmaxf(v, ALPHA*v);
            s = fmaf(v, __ldg(fc1 + f), s);
        }
        ts[n] = 1.f/(1.f + __expf(-s));
    }
    __syncthreads();

    // ---- y = t @ fc2 -------------------------------------------------------
    if (t < NN) {
        int j = t;
        float a = 0.f;
        #pragma unroll 2
        for (int n = 0; n < NN; n++) a = fmaf(ts[n], __ldg(fc2 + n*NN + j), a);
        ys[j] = a;
    }
    __syncthreads();

    // ---- final: out[b] = sum_j t[j]*softmax(y)[j] --------------------------
    if (t < 32) {
        float yv[4];
        float m = -1e30f;
        #pragma unroll
        for (int q = 0; q < 4; q++) {
            int j = q*32 + t;
            yv[q] = (j < NN) ? ys[j] : -1e30f;
            m = fmaxf(m, yv[q]);
        }
        m = wred_max(m);
        float S = 0.f, T = 0.f;
        #pragma unroll
        for (int q = 0; q < 4; q++) {
            int j = q*32 + t;
            if (j < NN) {
                float p = __expf(yv[q] - m);
                S += p;
                T = fmaf(ts[j], p, T);
            }
        }
        S = wred_sum(S); T = wred_sum(T);
        if (t == 0) out[b] = T / S;
    }
}

extern "C" void kernel_launch(void* const* d_in, const int* in_sizes, int n_in,
                              void* d_out, int out_size) {
    (void)in_sizes; (void)n_in; (void)out_size;
    const float* X   = (const float*)d_in[0];
    const float* A   = (const float*)d_in[1];
    const float* M   = (const float*)d_in[2];
    const float* W1  = (const float*)d_in[3];
    const float* as1 = (const float*)d_in[4];
    const float* an1 = (const float*)d_in[5];
    const float* b1  = (const float*)d_in[6];
    const float* W2  = (const float*)d_in[7];
    const float* as2 = (const float*)d_in[8];
    const float* an2 = (const float*)d_in[9];
    const float* b2  = (const float*)d_in[10];
    const float* fc1 = (const float*)d_in[11];
    const float* fc2 = (const float*)d_in[12];

    cudaFuncSetAttribute(gat_kernel, cudaFuncAttributeMaxDynamicSharedMemorySize, SMEM_BYTES);

    prep_kernel<<<(NN*HF1 + 255)/256, 256>>>(M, W1, W2);
    gat_kernel<<<BB, NT, SMEM_BYTES>>>(X, A, as1, an1, b1,
                                       as2, an2, b2, fc1, fc2,
                                       (float*)d_out);
}